// round 6
// baseline (speedup 1.0000x reference)
#include <cuda_runtime.h>
#include <cuda_bf16.h>
#include <cstdint>
#include <cstddef>

// ---------------- problem constants ----------------
#define TT     256
#define BBATCH 32
#define NFEAT  1024
#define NHEAD  16
#define HDIM   64
#define FFD    4096
#define LLAY   6
#define MROWS  (TT*BBATCH)            // 8192 token rows

// packed split-weight offsets (elements)
#define LEN_WQKV (LLAY*3*NFEAT*NFEAT)
#define OFF_WO   (LEN_WQKV)
#define LEN_WO   (LLAY*NFEAT*NFEAT)
#define OFF_W1   (OFF_WO + LEN_WO)
#define LEN_W1   (LLAY*FFD*NFEAT)
#define OFF_W2   (OFF_W1 + LEN_W1)
#define LEN_W2   (LLAY*NFEAT*FFD)
#define WTOT     (OFF_W2 + LEN_W2)

// ---------------- device scratch (static; no runtime allocation) ----------------
__device__ __nv_bfloat16 g_whi[WTOT];
__device__ __nv_bfloat16 g_wlo[WTOT];
__device__ __nv_bfloat16 g_hhi[MROWS*NFEAT];
__device__ __nv_bfloat16 g_hlo[MROWS*NFEAT];
__device__ __nv_bfloat16 g_fhi[(size_t)MROWS*FFD];
__device__ __nv_bfloat16 g_flo[(size_t)MROWS*FFD];
__device__ float g_qkv[(size_t)MROWS*3*NFEAT];
__device__ float g_x[MROWS*NFEAT];
__device__ float g_maskT[TT*TT];

// ---------------- helpers ----------------
__device__ __forceinline__ uint32_t smem_u32(const void* p) {
    uint32_t a;
    asm("{ .reg .u64 t; cvta.to.shared.u64 t, %1; cvt.u32.u64 %0, t; }" : "=r"(a) : "l"(p));
    return a;
}

#define LDSM4(r, addr) \
    asm volatile("ldmatrix.sync.aligned.m8n8.x4.shared.b16 {%0,%1,%2,%3}, [%4];" \
        : "=r"((r)[0]), "=r"((r)[1]), "=r"((r)[2]), "=r"((r)[3]) : "r"(addr))

#define MMA16816(d, a, b0r, b1r) \
    asm volatile("mma.sync.aligned.m16n8k16.row.col.f32.bf16.bf16.f32 " \
        "{%0,%1,%2,%3},{%4,%5,%6,%7},{%8,%9},{%0,%1,%2,%3};" \
        : "+f"((d)[0]), "+f"((d)[1]), "+f"((d)[2]), "+f"((d)[3]) \
        : "r"((a)[0]), "r"((a)[1]), "r"((a)[2]), "r"((a)[3]), "r"(b0r), "r"(b1r))

#define CP16(dst, src) \
    asm volatile("cp.async.cg.shared.global [%0], [%1], 16;" :: "r"((uint32_t)(dst)), "l"(src))
#define CP_COMMIT() asm volatile("cp.async.commit_group;" ::: "memory")
#define CP_WAIT1()  asm volatile("cp.async.wait_group 1;" ::: "memory")

// ================= pipelined GEMM: C[M,Nout] = A[M,K] * B[Nout,K]^T, 3-pass bf16 split =================
// BM=128, BN=128, BK=32, 256 threads (8 warps: 2 x 4), warp tile 64x32, 3-stage cp.async pipeline.
#define SAS 40                      // smem row stride in bf16 (80B, conflict-free ldmatrix)
#define ARR_B (128*SAS*2)           // 10240 B per operand tile
#define STGB  (4*ARR_B)             // 40960 B per stage (Ah,Al,Bh,Bl)
#define NSTG  3
#define SMEM_G (NSTG*STGB)          // 122880 B

__global__ __launch_bounds__(256, 1)
void gemm3p(const __nv_bfloat16* __restrict__ Ahi, const __nv_bfloat16* __restrict__ Alo,
            const __nv_bfloat16* __restrict__ Bhi, const __nv_bfloat16* __restrict__ Blo,
            int K, int ldout,
            const float* __restrict__ bias,
            const float* __restrict__ res, float* __restrict__ outF,
            __nv_bfloat16* __restrict__ outHi, __nv_bfloat16* __restrict__ outLo,
            int epi)   // 0: C+b   1: C+b+res   2: relu(C+b) -> bf16 hi/lo split
{
    extern __shared__ __align__(128) char smem[];
    const int tid = threadIdx.x, lane = tid & 31, wid = tid >> 5;
    const int wm = wid >> 2, wn = wid & 3;
    const int m0 = blockIdx.y * 128, n0 = blockIdx.x * 128;
    const uint32_t sb = smem_u32(smem);

    float acc[4][4][4];
    #pragma unroll
    for (int mi = 0; mi < 4; mi++)
        #pragma unroll
        for (int ni = 0; ni < 4; ni++)
            #pragma unroll
            for (int j = 0; j < 4; j++) acc[mi][ni][j] = 0.f;

    // per-thread load mapping: 512 x 16B chunks per operand tile
    const int lrow = tid >> 2, lcc = tid & 3;       // +128 rows via i
    // ldmatrix per-thread source rows
    const int arow  = wm * 64 + (lane & 15);
    const int akoff = (lane >> 4) * 8;
    const int brow  = wn * 32 + (lane & 7) + ((lane >> 4) << 3);
    const int bkoff = ((lane >> 3) & 1) * 8;

    const int S = K >> 5;   // 32-wide K stages

    auto load_stage = [&](int s) {
        const int kt = s << 5;
        const uint32_t stg = sb + (uint32_t)(s % NSTG) * STGB;
        #pragma unroll
        for (int i = 0; i < 2; i++) {
            int r = lrow + i * 64;
            uint32_t d = (uint32_t)(r * (SAS * 2) + lcc * 16);
            size_t ga = (size_t)(m0 + r) * K + kt + lcc * 8;
            size_t gb = (size_t)(n0 + r) * K + kt + lcc * 8;
            CP16(stg + d,             Ahi + ga);
            CP16(stg + ARR_B + d,     Alo + ga);
            CP16(stg + 2 * ARR_B + d, Bhi + gb);
            CP16(stg + 3 * ARR_B + d, Blo + gb);
        }
    };

    load_stage(0); CP_COMMIT();
    load_stage(1); CP_COMMIT();

    for (int s = 0; s < S; s++) {
        CP_WAIT1();
        __syncthreads();

        const uint32_t stg = sb + (uint32_t)(s % NSTG) * STGB;
        const uint32_t bAh = stg, bAl = stg + ARR_B, bBh = stg + 2 * ARR_B, bBl = stg + 3 * ARR_B;
        #pragma unroll
        for (int ks = 0; ks < 2; ks++) {
            uint32_t ah[4][4], al[4][4], bh[2][4], bl[2][4];
            #pragma unroll
            for (int mi = 0; mi < 4; mi++) {
                uint32_t off = (uint32_t)(((arow + mi * 16) * SAS + ks * 16 + akoff) * 2);
                LDSM4(ah[mi], bAh + off);
                LDSM4(al[mi], bAl + off);
            }
            #pragma unroll
            for (int nj = 0; nj < 2; nj++) {
                uint32_t off = (uint32_t)(((brow + nj * 16) * SAS + ks * 16 + bkoff) * 2);
                LDSM4(bh[nj], bBh + off);
                LDSM4(bl[nj], bBl + off);
            }
            #pragma unroll
            for (int mi = 0; mi < 4; mi++)
                #pragma unroll
                for (int ni = 0; ni < 4; ni++) {
                    const int nj = ni >> 1, s2 = (ni & 1) * 2;
                    MMA16816(acc[mi][ni], ah[mi], bh[nj][s2], bh[nj][s2 + 1]);
                    MMA16816(acc[mi][ni], ah[mi], bl[nj][s2], bl[nj][s2 + 1]);
                    MMA16816(acc[mi][ni], al[mi], bh[nj][s2], bh[nj][s2 + 1]);
                }
        }
        __syncthreads();
        if (s + 2 < S) load_stage(s + 2);
        CP_COMMIT();          // always commit so wait_group counting stays exact
    }

    // ---- epilogue ----
    const int gid = lane >> 2, tig = lane & 3;
    #pragma unroll
    for (int mi = 0; mi < 4; mi++)
        #pragma unroll
        for (int ni = 0; ni < 4; ni++) {
            int r0 = m0 + wm * 64 + mi * 16 + gid;
            int c0 = n0 + wn * 32 + ni * 8 + tig * 2;
            float b0 = bias[c0], b1 = bias[c0 + 1];
            #pragma unroll
            for (int half = 0; half < 2; half++) {
                int r = r0 + half * 8;
                float v0 = acc[mi][ni][half * 2 + 0] + b0;
                float v1 = acc[mi][ni][half * 2 + 1] + b1;
                size_t idx = (size_t)r * ldout + c0;
                if (epi == 0) {
                    outF[idx] = v0; outF[idx + 1] = v1;
                } else if (epi == 1) {
                    outF[idx]     = v0 + res[idx];
                    outF[idx + 1] = v1 + res[idx + 1];
                } else {
                    v0 = fmaxf(v0, 0.f); v1 = fmaxf(v1, 0.f);
                    __nv_bfloat16 h0 = __float2bfloat16(v0);
                    __nv_bfloat16 h1 = __float2bfloat16(v1);
                    outHi[idx]     = h0;
                    outHi[idx + 1] = h1;
                    outLo[idx]     = __float2bfloat16(v0 - __bfloat162float(h0));
                    outLo[idx + 1] = __float2bfloat16(v1 - __bfloat162float(h1));
                }
            }
        }
}

// ---------------- LayerNorm (row = block). mode 0: bf16 split; mode 1: fp32 ----------------
__global__ __launch_bounds__(256)
void ln_kernel(const float* __restrict__ x, const float* __restrict__ g, const float* __restrict__ b,
               __nv_bfloat16* hi, __nv_bfloat16* lo, float* outf, int mode)
{
    __shared__ float red[16];
    const int row = blockIdx.x, tid = threadIdx.x;
    float4 v = ((const float4*)(x + (size_t)row * NFEAT))[tid];
    float s  = v.x + v.y + v.z + v.w;
    float sq = v.x * v.x + v.y * v.y + v.z * v.z + v.w * v.w;
    #pragma unroll
    for (int o = 16; o; o >>= 1) { s += __shfl_xor_sync(~0u, s, o); sq += __shfl_xor_sync(~0u, sq, o); }
    if ((tid & 31) == 0) { red[tid >> 5] = s; red[8 + (tid >> 5)] = sq; }
    __syncthreads();
    if (tid == 0) {
        float a = 0.f, c = 0.f;
        #pragma unroll
        for (int i = 0; i < 8; i++) { a += red[i]; c += red[8 + i]; }
        red[0] = a; red[8] = c;
    }
    __syncthreads();
    float mean = red[0] * (1.f / NFEAT);
    float var  = red[8] * (1.f / NFEAT) - mean * mean;
    float rs   = rsqrtf(var + 1e-5f);
    float4 gg = ((const float4*)g)[tid];
    float4 bb = ((const float4*)b)[tid];
    float y[4];
    y[0] = (v.x - mean) * rs * gg.x + bb.x;
    y[1] = (v.y - mean) * rs * gg.y + bb.y;
    y[2] = (v.z - mean) * rs * gg.z + bb.z;
    y[3] = (v.w - mean) * rs * gg.w + bb.w;
    size_t o0 = (size_t)row * NFEAT + tid * 4;
    if (mode == 0) {
        #pragma unroll
        for (int j = 0; j < 4; j++) {
            __nv_bfloat16 h = __float2bfloat16(y[j]);
            hi[o0 + j] = h;
            lo[o0 + j] = __float2bfloat16(y[j] - __bfloat162float(h));
        }
    } else {
        ((float4*)(outf + (size_t)row * NFEAT))[tid] = make_float4(y[0], y[1], y[2], y[3]);
    }
}

// ---------------- Attention: one block per (b,h), one query row per thread ----------------
__global__ __launch_bounds__(256, 1)
void attn_kernel(const float* __restrict__ qkv, const float* __restrict__ maskT,
                 __nv_bfloat16* __restrict__ oHi, __nv_bfloat16* __restrict__ oLo)
{
    extern __shared__ float sm[];
    float* sK = sm;
    float* sV = sm + TT * HDIM;
    const int b = blockIdx.x >> 4, h = blockIdx.x & 15;
    const int tid = threadIdx.x;
    const float scale = 0.125f;

    for (int i = tid; i < TT * HDIM; i += 256) {
        int s = i >> 6, d = i & 63;
        size_t base = (size_t)(s * BBATCH + b) * (3 * NFEAT) + h * HDIM + d;
        sK[i] = qkv[base + NFEAT];
        sV[i] = qkv[base + 2 * NFEAT];
    }
    __syncthreads();

    const int t = tid;
    float q[64], o[64];
    size_t qb = (size_t)(t * BBATCH + b) * (3 * NFEAT) + h * HDIM;
    #pragma unroll
    for (int d = 0; d < 64; d++) { q[d] = qkv[qb + d] * scale; o[d] = 0.f; }

    float m = -1e30f, ssum = 0.f;
    for (int s = 0; s < TT; s++) {
        const float4* k4 = (const float4*)(sK + s * HDIM);
        float x = 0.f;
        #pragma unroll
        for (int d4 = 0; d4 < 16; d4++) {
            float4 kk = k4[d4];
            x += q[d4 * 4 + 0] * kk.x + q[d4 * 4 + 1] * kk.y
               + q[d4 * 4 + 2] * kk.z + q[d4 * 4 + 3] * kk.w;
        }
        x += maskT[s * TT + t];
        float p;
        if (x > m) {
            float f = __expf(m - x);
            ssum *= f;
            #pragma unroll
            for (int d = 0; d < 64; d++) o[d] *= f;
            m = x; p = 1.f;
        } else {
            p = __expf(x - m);
        }
        ssum += p;
        const float4* v4 = (const float4*)(sV + s * HDIM);
        #pragma unroll
        for (int d4 = 0; d4 < 16; d4++) {
            float4 vv = v4[d4];
            o[d4 * 4 + 0] += p * vv.x; o[d4 * 4 + 1] += p * vv.y;
            o[d4 * 4 + 2] += p * vv.z; o[d4 * 4 + 3] += p * vv.w;
        }
    }
    float inv = 1.f / ssum;
    size_t ob = (size_t)(t * BBATCH + b) * NFEAT + h * HDIM;
    #pragma unroll
    for (int d = 0; d < 64; d++) {
        float v = o[d] * inv;
        __nv_bfloat16 hh = __float2bfloat16(v);
        oHi[ob + d] = hh;
        oLo[ob + d] = __float2bfloat16(v - __bfloat162float(hh));
    }
}

// ---------------- small utility kernels ----------------
__global__ void split_kernel(const float* __restrict__ src, __nv_bfloat16* __restrict__ hi,
                             __nv_bfloat16* __restrict__ lo, int n4)
{
    int i = blockIdx.x * 256 + threadIdx.x;
    if (i >= n4) return;
    float4 v = ((const float4*)src)[i];
    float a[4] = { v.x, v.y, v.z, v.w };
    size_t o = (size_t)i * 4;
    #pragma unroll
    for (int j = 0; j < 4; j++) {
        __nv_bfloat16 h = __float2bfloat16(a[j]);
        hi[o + j] = h;
        lo[o + j] = __float2bfloat16(a[j] - __bfloat162float(h));
    }
}

__global__ void copy_kernel(const float* __restrict__ src, float* __restrict__ dst, int n4)
{
    int i = blockIdx.x * 256 + threadIdx.x;
    if (i < n4) ((float4*)dst)[i] = ((const float4*)src)[i];
}

__global__ void maskT_kernel(const float* __restrict__ m, float* __restrict__ mt)
{
    int i = blockIdx.x * 256 + threadIdx.x;
    int t = i >> 8, s = i & 255;
    mt[s * TT + t] = m[i];
}

// ---------------- host driver ----------------
extern "C" void kernel_launch(void* const* d_in, const int* in_sizes, int n_in,
                              void* d_out, int out_size)
{
    const float* src   = (const float*)d_in[0];
    const float* mask  = (const float*)d_in[1];
    const float* Wqkv  = (const float*)d_in[2];
    const float* bqkv  = (const float*)d_in[3];
    const float* Wo    = (const float*)d_in[4];
    const float* bo    = (const float*)d_in[5];
    const float* ln1g  = (const float*)d_in[6];
    const float* ln1b  = (const float*)d_in[7];
    const float* ln2g  = (const float*)d_in[8];
    const float* ln2b  = (const float*)d_in[9];
    const float* W1    = (const float*)d_in[10];
    const float* b1    = (const float*)d_in[11];
    const float* W2    = (const float*)d_in[12];
    const float* b2    = (const float*)d_in[13];
    const float* lnfg  = (const float*)d_in[14];
    const float* lnfb  = (const float*)d_in[15];
    float* out = (float*)d_out;

    void *p_whi, *p_wlo, *p_hhi, *p_hlo, *p_fhi, *p_flo, *p_qkv, *p_x, *p_mt;
    cudaGetSymbolAddress(&p_whi, g_whi);
    cudaGetSymbolAddress(&p_wlo, g_wlo);
    cudaGetSymbolAddress(&p_hhi, g_hhi);
    cudaGetSymbolAddress(&p_hlo, g_hlo);
    cudaGetSymbolAddress(&p_fhi, g_fhi);
    cudaGetSymbolAddress(&p_flo, g_flo);
    cudaGetSymbolAddress(&p_qkv, g_qkv);
    cudaGetSymbolAddress(&p_x,   g_x);
    cudaGetSymbolAddress(&p_mt,  g_maskT);
    __nv_bfloat16* whi = (__nv_bfloat16*)p_whi;
    __nv_bfloat16* wlo = (__nv_bfloat16*)p_wlo;
    __nv_bfloat16* hhi = (__nv_bfloat16*)p_hhi;
    __nv_bfloat16* hlo = (__nv_bfloat16*)p_hlo;
    __nv_bfloat16* fhi = (__nv_bfloat16*)p_fhi;
    __nv_bfloat16* flo = (__nv_bfloat16*)p_flo;
    float* qkv = (float*)p_qkv;
    float* x   = (float*)p_x;
    float* mt  = (float*)p_mt;

    cudaFuncSetAttribute(attn_kernel, cudaFuncAttributeMaxDynamicSharedMemorySize,
                         2 * TT * HDIM * (int)sizeof(float));
    cudaFuncSetAttribute(gemm3p, cudaFuncAttributeMaxDynamicSharedMemorySize, SMEM_G);

    // split weights into bf16 hi/lo
    auto splitw = [&](const float* s, size_t off, size_t len) {
        int n4 = (int)(len / 4);
        split_kernel<<<(n4 + 255) / 256, 256>>>(s, whi + off, wlo + off, n4);
    };
    splitw(Wqkv, 0,      LEN_WQKV);
    splitw(Wo,   OFF_WO, LEN_WO);
    splitw(W1,   OFF_W1, LEN_W1);
    splitw(W2,   OFF_W2, LEN_W2);

    copy_kernel<<<(MROWS * NFEAT / 4 + 255) / 256, 256>>>(src, x, MROWS * NFEAT / 4);
    maskT_kernel<<<TT * TT / 256, 256>>>(mask, mt);

    for (int l = 0; l < LLAY; l++) {
        // --- attention block ---
        ln_kernel<<<MROWS, 256>>>(x, ln1g + l * NFEAT, ln1b + l * NFEAT, hhi, hlo, nullptr, 0);
        gemm3p<<<dim3(3 * NFEAT / 128, MROWS / 128), 256, SMEM_G>>>(
            hhi, hlo,
            whi + (size_t)l * 3 * NFEAT * NFEAT, wlo + (size_t)l * 3 * NFEAT * NFEAT,
            NFEAT, 3 * NFEAT, bqkv + l * 3 * NFEAT,
            nullptr, qkv, nullptr, nullptr, 0);
        attn_kernel<<<BBATCH * NHEAD, 256, 2 * TT * HDIM * sizeof(float)>>>(qkv, mt, hhi, hlo);
        gemm3p<<<dim3(NFEAT / 128, MROWS / 128), 256, SMEM_G>>>(
            hhi, hlo,
            whi + OFF_WO + (size_t)l * NFEAT * NFEAT, wlo + OFF_WO + (size_t)l * NFEAT * NFEAT,
            NFEAT, NFEAT, bo + l * NFEAT,
            x, x, nullptr, nullptr, 1);
        // --- FFN block ---
        ln_kernel<<<MROWS, 256>>>(x, ln2g + l * NFEAT, ln2b + l * NFEAT, hhi, hlo, nullptr, 0);
        gemm3p<<<dim3(FFD / 128, MROWS / 128), 256, SMEM_G>>>(
            hhi, hlo,
            whi + OFF_W1 + (size_t)l * FFD * NFEAT, wlo + OFF_W1 + (size_t)l * FFD * NFEAT,
            NFEAT, FFD, b1 + l * FFD,
            nullptr, nullptr, fhi, flo, 2);
        gemm3p<<<dim3(NFEAT / 128, MROWS / 128), 256, SMEM_G>>>(
            fhi, flo,
            whi + OFF_W2 + (size_t)l * NFEAT * FFD, wlo + OFF_W2 + (size_t)l * NFEAT * FFD,
            FFD, NFEAT, b2 + l * NFEAT,
            x, x, nullptr, nullptr, 1);
    }
    ln_kernel<<<MROWS, 256>>>(x, lnfg, lnfb, nullptr, nullptr, out, 1);
}

// round 7
// speedup vs baseline: 1.6595x; 1.6595x over previous
#include <cuda_runtime.h>
#include <cuda_bf16.h>
#include <cstdint>
#include <cstddef>

// ---------------- problem constants ----------------
#define TT     256
#define BBATCH 32
#define NFEAT  1024
#define NHEAD  16
#define HDIM   64
#define FFD    4096
#define LLAY   6
#define MROWS  (TT*BBATCH)            // 8192 token rows

// packed split-weight offsets (elements)
#define LEN_WQKV (LLAY*3*NFEAT*NFEAT)
#define OFF_WO   (LEN_WQKV)
#define LEN_WO   (LLAY*NFEAT*NFEAT)
#define OFF_W1   (OFF_WO + LEN_WO)
#define LEN_W1   (LLAY*FFD*NFEAT)
#define OFF_W2   (OFF_W1 + LEN_W1)
#define LEN_W2   (LLAY*NFEAT*FFD)
#define WTOT     (OFF_W2 + LEN_W2)

// ---------------- device scratch (static; no runtime allocation) ----------------
__device__ __nv_bfloat16 g_whi[WTOT];
__device__ __nv_bfloat16 g_wlo[WTOT];
__device__ __nv_bfloat16 g_hhi[MROWS*NFEAT];
__device__ __nv_bfloat16 g_hlo[MROWS*NFEAT];
__device__ __nv_bfloat16 g_fhi[(size_t)MROWS*FFD];
__device__ __nv_bfloat16 g_flo[(size_t)MROWS*FFD];
__device__ float g_qkv[(size_t)MROWS*3*NFEAT];
__device__ float g_x[MROWS*NFEAT];
__device__ float g_maskT[TT*TT];

// ---------------- helpers ----------------
__device__ __forceinline__ uint32_t smem_u32(const void* p) {
    uint32_t a;
    asm("{ .reg .u64 t; cvta.to.shared.u64 t, %1; cvt.u32.u64 %0, t; }" : "=r"(a) : "l"(p));
    return a;
}

#define LDSM4(r, addr) \
    asm volatile("ldmatrix.sync.aligned.m8n8.x4.shared.b16 {%0,%1,%2,%3}, [%4];" \
        : "=r"((r)[0]), "=r"((r)[1]), "=r"((r)[2]), "=r"((r)[3]) : "r"(addr))

#define MMA16816(d, a, b0r, b1r) \
    asm volatile("mma.sync.aligned.m16n8k16.row.col.f32.bf16.bf16.f32 " \
        "{%0,%1,%2,%3},{%4,%5,%6,%7},{%8,%9},{%0,%1,%2,%3};" \
        : "+f"((d)[0]), "+f"((d)[1]), "+f"((d)[2]), "+f"((d)[3]) \
        : "r"((a)[0]), "r"((a)[1]), "r"((a)[2]), "r"((a)[3]), "r"(b0r), "r"(b1r))

#define CP16(dst, src) \
    asm volatile("cp.async.cg.shared.global [%0], [%1], 16;" :: "r"((uint32_t)(dst)), "l"(src))
#define CP_COMMIT() asm volatile("cp.async.commit_group;" ::: "memory")
#define CP_WAIT0()  asm volatile("cp.async.wait_group 0;" ::: "memory")

// ================= pipelined GEMM: C[M,Nout] = A[M,K] * B[Nout,K]^T, 3-pass bf16 split =================
// BM=64, BN=128, BK=32, 256 threads (8 warps: 2 x 4), warp tile 32x32,
// 2-stage cp.async double buffer, targets 2 CTAs/SM.
#define SAS 40                         // smem row stride in bf16 (80B, conflict-free ldmatrix)
#define A_BYTES (64*SAS*2)             // 5120 B per A operand (hi or lo)
#define B_BYTES (128*SAS*2)            // 10240 B per B operand
#define STGB (2*A_BYTES + 2*B_BYTES)   // 30720 B per stage
#define SMEM_G (2*STGB)                // 61440 B

__global__ __launch_bounds__(256, 2)
void gemm3p(const __nv_bfloat16* __restrict__ Ahi, const __nv_bfloat16* __restrict__ Alo,
            const __nv_bfloat16* __restrict__ Bhi, const __nv_bfloat16* __restrict__ Blo,
            int K, int ldout,
            const float* __restrict__ bias,
            const float* __restrict__ res, float* __restrict__ outF,
            __nv_bfloat16* __restrict__ outHi, __nv_bfloat16* __restrict__ outLo,
            int epi)   // 0: C+b   1: C+b+res   2: relu(C+b) -> bf16 hi/lo split
{
    extern __shared__ __align__(128) char smem[];
    const int tid = threadIdx.x, lane = tid & 31, wid = tid >> 5;
    const int wm = wid >> 2, wn = wid & 3;            // 2 x 4 warp grid
    const int m0 = blockIdx.y * 64, n0 = blockIdx.x * 128;
    const uint32_t sb = smem_u32(smem);

    float acc[2][4][4];
    #pragma unroll
    for (int mi = 0; mi < 2; mi++)
        #pragma unroll
        for (int ni = 0; ni < 4; ni++)
            #pragma unroll
            for (int j = 0; j < 4; j++) acc[mi][ni][j] = 0.f;

    // per-thread load mapping
    const int lrow = tid >> 2, lcc = tid & 3;
    // ldmatrix per-thread source rows (mapping validated in R3)
    const int arow  = wm * 32 + (lane & 15);
    const int akoff = (lane >> 4) * 8;
    const int brow  = wn * 32 + (lane & 7) + ((lane >> 4) << 3);
    const int bkoff = ((lane >> 3) & 1) * 8;

    const int S = K >> 5;   // 32-wide K stages

    auto load_stage = [&](int s) {
        const int kt = s << 5;
        const uint32_t stg = sb + (uint32_t)(s & 1) * STGB;
        // A: 64 rows x 32 -> 256 x 16B chunks (1 per thread), hi+lo
        {
            uint32_t d = (uint32_t)(lrow * (SAS * 2) + lcc * 16);
            size_t ga = (size_t)(m0 + lrow) * K + kt + lcc * 8;
            CP16(stg + d,           Ahi + ga);
            CP16(stg + A_BYTES + d, Alo + ga);
        }
        // B: 128 rows x 32 -> 512 x 16B chunks (2 per thread), hi+lo
        #pragma unroll
        for (int i = 0; i < 2; i++) {
            int r = lrow + i * 64;
            uint32_t d = (uint32_t)(r * (SAS * 2) + lcc * 16);
            size_t gb = (size_t)(n0 + r) * K + kt + lcc * 8;
            CP16(stg + 2 * A_BYTES + d,           Bhi + gb);
            CP16(stg + 2 * A_BYTES + B_BYTES + d, Blo + gb);
        }
    };

    load_stage(0); CP_COMMIT();

    for (int s = 0; s < S; s++) {
        CP_WAIT0();
        __syncthreads();
        if (s + 1 < S) { load_stage(s + 1); CP_COMMIT(); }

        const uint32_t stg = sb + (uint32_t)(s & 1) * STGB;
        const uint32_t bAh = stg, bAl = stg + A_BYTES;
        const uint32_t bBh = stg + 2 * A_BYTES, bBl = stg + 2 * A_BYTES + B_BYTES;
        #pragma unroll
        for (int ks = 0; ks < 2; ks++) {
            uint32_t ah[2][4], al[2][4], bh[2][4], bl[2][4];
            #pragma unroll
            for (int mi = 0; mi < 2; mi++) {
                uint32_t off = (uint32_t)(((arow + mi * 16) * SAS + ks * 16 + akoff) * 2);
                LDSM4(ah[mi], bAh + off);
                LDSM4(al[mi], bAl + off);
            }
            #pragma unroll
            for (int nj = 0; nj < 2; nj++) {
                uint32_t off = (uint32_t)(((brow + nj * 16) * SAS + ks * 16 + bkoff) * 2);
                LDSM4(bh[nj], bBh + off);
                LDSM4(bl[nj], bBl + off);
            }
            #pragma unroll
            for (int mi = 0; mi < 2; mi++)
                #pragma unroll
                for (int ni = 0; ni < 4; ni++) {
                    const int nj = ni >> 1, s2 = (ni & 1) * 2;
                    MMA16816(acc[mi][ni], ah[mi], bh[nj][s2], bh[nj][s2 + 1]);
                    MMA16816(acc[mi][ni], ah[mi], bl[nj][s2], bl[nj][s2 + 1]);
                    MMA16816(acc[mi][ni], al[mi], bh[nj][s2], bh[nj][s2 + 1]);
                }
        }
    }

    // ---- epilogue (mapping validated in R3) ----
    const int gid = lane >> 2, tig = lane & 3;
    #pragma unroll
    for (int mi = 0; mi < 2; mi++)
        #pragma unroll
        for (int ni = 0; ni < 4; ni++) {
            int r0 = m0 + wm * 32 + mi * 16 + gid;
            int c0 = n0 + wn * 32 + ni * 8 + tig * 2;
            float b0 = bias[c0], b1 = bias[c0 + 1];
            #pragma unroll
            for (int half = 0; half < 2; half++) {
                int r = r0 + half * 8;
                float v0 = acc[mi][ni][half * 2 + 0] + b0;
                float v1 = acc[mi][ni][half * 2 + 1] + b1;
                size_t idx = (size_t)r * ldout + c0;
                if (epi == 0) {
                    outF[idx] = v0; outF[idx + 1] = v1;
                } else if (epi == 1) {
                    outF[idx]     = v0 + res[idx];
                    outF[idx + 1] = v1 + res[idx + 1];
                } else {
                    v0 = fmaxf(v0, 0.f); v1 = fmaxf(v1, 0.f);
                    __nv_bfloat16 h0 = __float2bfloat16(v0);
                    __nv_bfloat16 h1 = __float2bfloat16(v1);
                    outHi[idx]     = h0;
                    outHi[idx + 1] = h1;
                    outLo[idx]     = __float2bfloat16(v0 - __bfloat162float(h0));
                    outLo[idx + 1] = __float2bfloat16(v1 - __bfloat162float(h1));
                }
            }
        }
}

// ---------------- LayerNorm (row = block). mode 0: bf16 split; mode 1: fp32 ----------------
__global__ __launch_bounds__(256)
void ln_kernel(const float* __restrict__ x, const float* __restrict__ g, const float* __restrict__ b,
               __nv_bfloat16* hi, __nv_bfloat16* lo, float* outf, int mode)
{
    __shared__ float red[16];
    const int row = blockIdx.x, tid = threadIdx.x;
    float4 v = ((const float4*)(x + (size_t)row * NFEAT))[tid];
    float s  = v.x + v.y + v.z + v.w;
    float sq = v.x * v.x + v.y * v.y + v.z * v.z + v.w * v.w;
    #pragma unroll
    for (int o = 16; o; o >>= 1) { s += __shfl_xor_sync(~0u, s, o); sq += __shfl_xor_sync(~0u, sq, o); }
    if ((tid & 31) == 0) { red[tid >> 5] = s; red[8 + (tid >> 5)] = sq; }
    __syncthreads();
    if (tid == 0) {
        float a = 0.f, c = 0.f;
        #pragma unroll
        for (int i = 0; i < 8; i++) { a += red[i]; c += red[8 + i]; }
        red[0] = a; red[8] = c;
    }
    __syncthreads();
    float mean = red[0] * (1.f / NFEAT);
    float var  = red[8] * (1.f / NFEAT) - mean * mean;
    float rs   = rsqrtf(var + 1e-5f);
    float4 gg = ((const float4*)g)[tid];
    float4 bb = ((const float4*)b)[tid];
    float y[4];
    y[0] = (v.x - mean) * rs * gg.x + bb.x;
    y[1] = (v.y - mean) * rs * gg.y + bb.y;
    y[2] = (v.z - mean) * rs * gg.z + bb.z;
    y[3] = (v.w - mean) * rs * gg.w + bb.w;
    size_t o0 = (size_t)row * NFEAT + tid * 4;
    if (mode == 0) {
        #pragma unroll
        for (int j = 0; j < 4; j++) {
            __nv_bfloat16 h = __float2bfloat16(y[j]);
            hi[o0 + j] = h;
            lo[o0 + j] = __float2bfloat16(y[j] - __bfloat162float(h));
        }
    } else {
        ((float4*)(outf + (size_t)row * NFEAT))[tid] = make_float4(y[0], y[1], y[2], y[3]);
    }
}

// ---------------- Attention: one block per (b,h), one query row per thread ----------------
__global__ __launch_bounds__(256, 1)
void attn_kernel(const float* __restrict__ qkv, const float* __restrict__ maskT,
                 __nv_bfloat16* __restrict__ oHi, __nv_bfloat16* __restrict__ oLo)
{
    extern __shared__ float sm[];
    float* sK = sm;
    float* sV = sm + TT * HDIM;
    const int b = blockIdx.x >> 4, h = blockIdx.x & 15;
    const int tid = threadIdx.x;
    const float scale = 0.125f;

    for (int i = tid; i < TT * HDIM; i += 256) {
        int s = i >> 6, d = i & 63;
        size_t base = (size_t)(s * BBATCH + b) * (3 * NFEAT) + h * HDIM + d;
        sK[i] = qkv[base + NFEAT];
        sV[i] = qkv[base + 2 * NFEAT];
    }
    __syncthreads();

    const int t = tid;
    float q[64], o[64];
    size_t qb = (size_t)(t * BBATCH + b) * (3 * NFEAT) + h * HDIM;
    #pragma unroll
    for (int d = 0; d < 64; d++) { q[d] = qkv[qb + d] * scale; o[d] = 0.f; }

    float m = -1e30f, ssum = 0.f;
    for (int s = 0; s < TT; s++) {
        const float4* k4 = (const float4*)(sK + s * HDIM);
        float x = 0.f;
        #pragma unroll
        for (int d4 = 0; d4 < 16; d4++) {
            float4 kk = k4[d4];
            x += q[d4 * 4 + 0] * kk.x + q[d4 * 4 + 1] * kk.y
               + q[d4 * 4 + 2] * kk.z + q[d4 * 4 + 3] * kk.w;
        }
        x += maskT[s * TT + t];
        float p;
        if (x > m) {
            float f = __expf(m - x);
            ssum *= f;
            #pragma unroll
            for (int d = 0; d < 64; d++) o[d] *= f;
            m = x; p = 1.f;
        } else {
            p = __expf(x - m);
        }
        ssum += p;
        const float4* v4 = (const float4*)(sV + s * HDIM);
        #pragma unroll
        for (int d4 = 0; d4 < 16; d4++) {
            float4 vv = v4[d4];
            o[d4 * 4 + 0] += p * vv.x; o[d4 * 4 + 1] += p * vv.y;
            o[d4 * 4 + 2] += p * vv.z; o[d4 * 4 + 3] += p * vv.w;
        }
    }
    float inv = 1.f / ssum;
    size_t ob = (size_t)(t * BBATCH + b) * NFEAT + h * HDIM;
    #pragma unroll
    for (int d = 0; d < 64; d++) {
        float v = o[d] * inv;
        __nv_bfloat16 hh = __float2bfloat16(v);
        oHi[ob + d] = hh;
        oLo[ob + d] = __float2bfloat16(v - __bfloat162float(hh));
    }
}

// ---------------- small utility kernels ----------------
__global__ void split_kernel(const float* __restrict__ src, __nv_bfloat16* __restrict__ hi,
                             __nv_bfloat16* __restrict__ lo, int n4)
{
    int i = blockIdx.x * 256 + threadIdx.x;
    if (i >= n4) return;
    float4 v = ((const float4*)src)[i];
    float a[4] = { v.x, v.y, v.z, v.w };
    size_t o = (size_t)i * 4;
    #pragma unroll
    for (int j = 0; j < 4; j++) {
        __nv_bfloat16 h = __float2bfloat16(a[j]);
        hi[o + j] = h;
        lo[o + j] = __float2bfloat16(a[j] - __bfloat162float(h));
    }
}

__global__ void copy_kernel(const float* __restrict__ src, float* __restrict__ dst, int n4)
{
    int i = blockIdx.x * 256 + threadIdx.x;
    if (i < n4) ((float4*)dst)[i] = ((const float4*)src)[i];
}

__global__ void maskT_kernel(const float* __restrict__ m, float* __restrict__ mt)
{
    int i = blockIdx.x * 256 + threadIdx.x;
    int t = i >> 8, s = i & 255;
    mt[s * TT + t] = m[i];
}

// ---------------- host driver ----------------
extern "C" void kernel_launch(void* const* d_in, const int* in_sizes, int n_in,
                              void* d_out, int out_size)
{
    const float* src   = (const float*)d_in[0];
    const float* mask  = (const float*)d_in[1];
    const float* Wqkv  = (const float*)d_in[2];
    const float* bqkv  = (const float*)d_in[3];
    const float* Wo    = (const float*)d_in[4];
    const float* bo    = (const float*)d_in[5];
    const float* ln1g  = (const float*)d_in[6];
    const float* ln1b  = (const float*)d_in[7];
    const float* ln2g  = (const float*)d_in[8];
    const float* ln2b  = (const float*)d_in[9];
    const float* W1    = (const float*)d_in[10];
    const float* b1    = (const float*)d_in[11];
    const float* W2    = (const float*)d_in[12];
    const float* b2    = (const float*)d_in[13];
    const float* lnfg  = (const float*)d_in[14];
    const float* lnfb  = (const float*)d_in[15];
    float* out = (float*)d_out;

    void *p_whi, *p_wlo, *p_hhi, *p_hlo, *p_fhi, *p_flo, *p_qkv, *p_x, *p_mt;
    cudaGetSymbolAddress(&p_whi, g_whi);
    cudaGetSymbolAddress(&p_wlo, g_wlo);
    cudaGetSymbolAddress(&p_hhi, g_hhi);
    cudaGetSymbolAddress(&p_hlo, g_hlo);
    cudaGetSymbolAddress(&p_fhi, g_fhi);
    cudaGetSymbolAddress(&p_flo, g_flo);
    cudaGetSymbolAddress(&p_qkv, g_qkv);
    cudaGetSymbolAddress(&p_x,   g_x);
    cudaGetSymbolAddress(&p_mt,  g_maskT);
    __nv_bfloat16* whi = (__nv_bfloat16*)p_whi;
    __nv_bfloat16* wlo = (__nv_bfloat16*)p_wlo;
    __nv_bfloat16* hhi = (__nv_bfloat16*)p_hhi;
    __nv_bfloat16* hlo = (__nv_bfloat16*)p_hlo;
    __nv_bfloat16* fhi = (__nv_bfloat16*)p_fhi;
    __nv_bfloat16* flo = (__nv_bfloat16*)p_flo;
    float* qkv = (float*)p_qkv;
    float* x   = (float*)p_x;
    float* mt  = (float*)p_mt;

    cudaFuncSetAttribute(attn_kernel, cudaFuncAttributeMaxDynamicSharedMemorySize,
                         2 * TT * HDIM * (int)sizeof(float));
    cudaFuncSetAttribute(gemm3p, cudaFuncAttributeMaxDynamicSharedMemorySize, SMEM_G);

    // split weights into bf16 hi/lo
    auto splitw = [&](const float* s, size_t off, size_t len) {
        int n4 = (int)(len / 4);
        split_kernel<<<(n4 + 255) / 256, 256>>>(s, whi + off, wlo + off, n4);
    };
    splitw(Wqkv, 0,      LEN_WQKV);
    splitw(Wo,   OFF_WO, LEN_WO);
    splitw(W1,   OFF_W1, LEN_W1);
    splitw(W2,   OFF_W2, LEN_W2);

    copy_kernel<<<(MROWS * NFEAT / 4 + 255) / 256, 256>>>(src, x, MROWS * NFEAT / 4);
    maskT_kernel<<<TT * TT / 256, 256>>>(mask, mt);

    for (int l = 0; l < LLAY; l++) {
        // --- attention block ---
        ln_kernel<<<MROWS, 256>>>(x, ln1g + l * NFEAT, ln1b + l * NFEAT, hhi, hlo, nullptr, 0);
        gemm3p<<<dim3(3 * NFEAT / 128, MROWS / 64), 256, SMEM_G>>>(
            hhi, hlo,
            whi + (size_t)l * 3 * NFEAT * NFEAT, wlo + (size_t)l * 3 * NFEAT * NFEAT,
            NFEAT, 3 * NFEAT, bqkv + l * 3 * NFEAT,
            nullptr, qkv, nullptr, nullptr, 0);
        attn_kernel<<<BBATCH * NHEAD, 256, 2 * TT * HDIM * sizeof(float)>>>(qkv, mt, hhi, hlo);
        gemm3p<<<dim3(NFEAT / 128, MROWS / 64), 256, SMEM_G>>>(
            hhi, hlo,
            whi + OFF_WO + (size_t)l * NFEAT * NFEAT, wlo + OFF_WO + (size_t)l * NFEAT * NFEAT,
            NFEAT, NFEAT, bo + l * NFEAT,
            x, x, nullptr, nullptr, 1);
        // --- FFN block ---
        ln_kernel<<<MROWS, 256>>>(x, ln2g + l * NFEAT, ln2b + l * NFEAT, hhi, hlo, nullptr, 0);
        gemm3p<<<dim3(FFD / 128, MROWS / 64), 256, SMEM_G>>>(
            hhi, hlo,
            whi + OFF_W1 + (size_t)l * FFD * NFEAT, wlo + OFF_W1 + (size_t)l * FFD * NFEAT,
            NFEAT, FFD, b1 + l * FFD,
            nullptr, nullptr, fhi, flo, 2);
        gemm3p<<<dim3(NFEAT / 128, MROWS / 64), 256, SMEM_G>>>(
            fhi, flo,
            whi + OFF_W2 + (size_t)l * NFEAT * FFD, wlo + OFF_W2 + (size_t)l * NFEAT * FFD,
            FFD, NFEAT, b2 + l * NFEAT,
            x, x, nullptr, nullptr, 1);
    }
    ln_kernel<<<MROWS, 256>>>(x, lnfg, lnfb, nullptr, nullptr, out, 1);
}

// round 9
// speedup vs baseline: 1.7428x; 1.0502x over previous
#include <cuda_runtime.h>
#include <cuda_bf16.h>
#include <cstdint>
#include <cstddef>

// ---------------- problem constants ----------------
#define TT     256
#define BBATCH 32
#define NFEAT  1024
#define NHEAD  16
#define HDIM   64
#define FFD    4096
#define LLAY   6
#define MROWS  (TT*BBATCH)            // 8192 token rows

// packed split-weight offsets (elements)
#define LEN_WQKV (LLAY*3*NFEAT*NFEAT)
#define OFF_WO   (LEN_WQKV)
#define LEN_WO   (LLAY*NFEAT*NFEAT)
#define OFF_W1   (OFF_WO + LEN_WO)
#define LEN_W1   (LLAY*FFD*NFEAT)
#define OFF_W2   (OFF_W1 + LEN_W1)
#define LEN_W2   (LLAY*NFEAT*FFD)
#define WTOT     (OFF_W2 + LEN_W2)

// ---------------- device scratch (static; no runtime allocation) ----------------
__device__ __nv_bfloat16 g_whi[WTOT];
__device__ __nv_bfloat16 g_wlo[WTOT];
__device__ __nv_bfloat16 g_hhi[MROWS*NFEAT];
__device__ __nv_bfloat16 g_hlo[MROWS*NFEAT];
__device__ __nv_bfloat16 g_fhi[(size_t)MROWS*FFD];
__device__ __nv_bfloat16 g_flo[(size_t)MROWS*FFD];
__device__ float g_qkv[(size_t)MROWS*3*NFEAT];
__device__ float g_x[MROWS*NFEAT];
__device__ float g_maskT[TT*TT];

// ---------------- helpers ----------------
__device__ __forceinline__ uint32_t smem_u32(const void* p) {
    uint32_t a;
    asm("{ .reg .u64 t; cvta.to.shared.u64 t, %1; cvt.u32.u64 %0, t; }" : "=r"(a) : "l"(p));
    return a;
}

#define LDSM4(r, addr) \
    asm volatile("ldmatrix.sync.aligned.m8n8.x4.shared.b16 {%0,%1,%2,%3}, [%4];" \
        : "=r"((r)[0]), "=r"((r)[1]), "=r"((r)[2]), "=r"((r)[3]) : "r"(addr))

#define MMA16816(d, a, b0r, b1r) \
    asm volatile("mma.sync.aligned.m16n8k16.row.col.f32.bf16.bf16.f32 " \
        "{%0,%1,%2,%3},{%4,%5,%6,%7},{%8,%9},{%0,%1,%2,%3};" \
        : "+f"((d)[0]), "+f"((d)[1]), "+f"((d)[2]), "+f"((d)[3]) \
        : "r"((a)[0]), "r"((a)[1]), "r"((a)[2]), "r"((a)[3]), "r"(b0r), "r"(b1r))

#define CP16(dst, src) \
    asm volatile("cp.async.cg.shared.global [%0], [%1], 16;" :: "r"((uint32_t)(dst)), "l"(src))
#define CP_COMMIT() asm volatile("cp.async.commit_group;" ::: "memory")
#define CP_WAIT0()  asm volatile("cp.async.wait_group 0;" ::: "memory")

// ========== pipelined GEMM: C[M,Nout] = A[M,K] * B[Nout,K]^T, 3-pass bf16 split ==========
// BM=128, BN=128, BK=32, 256 threads (8 warps: 2 x 4), warp tile 64x32,
// 2-stage cp.async double buffer, 2 CTAs/SM (160KB smem total).
#define SAS 40                          // smem row stride in bf16 (80B, conflict-free ldmatrix)
#define OP_BYTES (128*SAS*2)            // 10240 B per operand (hi or lo)
#define STGB (4*OP_BYTES)               // 40960 B per stage (Ah,Al,Bh,Bl)
#define SMEM_G (2*STGB)                 // 81920 B

__global__ __launch_bounds__(256, 2)
void gemm3p(const __nv_bfloat16* __restrict__ Ahi, const __nv_bfloat16* __restrict__ Alo,
            const __nv_bfloat16* __restrict__ Bhi, const __nv_bfloat16* __restrict__ Blo,
            int K, int ldout,
            const float* __restrict__ bias,
            const float* __restrict__ res, float* __restrict__ outF,
            __nv_bfloat16* __restrict__ outHi, __nv_bfloat16* __restrict__ outLo,
            int epi)   // 0: C+b   1: C+b+res   2: relu(C+b) -> bf16 hi/lo split
{
    extern __shared__ __align__(128) char smem[];
    const int tid = threadIdx.x, lane = tid & 31, wid = tid >> 5;
    const int wm = wid >> 2, wn = wid & 3;            // 2 x 4 warp grid, warp tile 64x32
    const int m0 = blockIdx.y * 128, n0 = blockIdx.x * 128;
    const uint32_t sb = smem_u32(smem);

    float acc[4][4][4];
    #pragma unroll
    for (int mi = 0; mi < 4; mi++)
        #pragma unroll
        for (int ni = 0; ni < 4; ni++)
            #pragma unroll
            for (int j = 0; j < 4; j++) acc[mi][ni][j] = 0.f;

    // per-thread load mapping: 512 x 16B chunks per operand (hi/lo), 2 per thread each
    const int lrow = tid >> 2, lcc = tid & 3;
    // ldmatrix per-thread source rows (mapping validated in R3)
    const int arow  = wm * 64 + (lane & 15);
    const int akoff = (lane >> 4) * 8;
    const int brow  = wn * 32 + (lane & 7) + ((lane >> 4) << 3);
    const int bkoff = ((lane >> 3) & 1) * 8;

    const int S = K >> 5;   // 32-wide K stages

    auto load_stage = [&](int s) {
        const int kt = s << 5;
        const uint32_t stg = sb + (uint32_t)(s & 1) * STGB;
        #pragma unroll
        for (int i = 0; i < 2; i++) {
            int r = lrow + i * 64;
            uint32_t d = (uint32_t)(r * (SAS * 2) + lcc * 16);
            size_t ga = (size_t)(m0 + r) * K + kt + lcc * 8;
            size_t gb = (size_t)(n0 + r) * K + kt + lcc * 8;
            CP16(stg + d,                Ahi + ga);
            CP16(stg + OP_BYTES + d,     Alo + ga);
            CP16(stg + 2 * OP_BYTES + d, Bhi + gb);
            CP16(stg + 3 * OP_BYTES + d, Blo + gb);
        }
    };

    load_stage(0); CP_COMMIT();

    for (int s = 0; s < S; s++) {
        CP_WAIT0();
        __syncthreads();
        if (s + 1 < S) { load_stage(s + 1); CP_COMMIT(); }

        const uint32_t stg = sb + (uint32_t)(s & 1) * STGB;
        const uint32_t bAh = stg, bAl = stg + OP_BYTES;
        const uint32_t bBh = stg + 2 * OP_BYTES, bBl = stg + 3 * OP_BYTES;
        #pragma unroll
        for (int ks = 0; ks < 2; ks++) {
            uint32_t ah[4][4], al[4][4], bh[2][4], bl[2][4];
            #pragma unroll
            for (int nj = 0; nj < 2; nj++) {
                uint32_t off = (uint32_t)(((brow + nj * 16) * SAS + ks * 16 + bkoff) * 2);
                LDSM4(bh[nj], bBh + off);
                LDSM4(bl[nj], bBl + off);
            }
            #pragma unroll
            for (int mi = 0; mi < 4; mi++) {
                uint32_t off = (uint32_t)(((arow + mi * 16) * SAS + ks * 16 + akoff) * 2);
                LDSM4(ah[mi], bAh + off);
                LDSM4(al[mi], bAl + off);
            }
            #pragma unroll
            for (int mi = 0; mi < 4; mi++)
                #pragma unroll
                for (int ni = 0; ni < 4; ni++) {
                    const int nj = ni >> 1, s2 = (ni & 1) * 2;
                    MMA16816(acc[mi][ni], ah[mi], bh[nj][s2], bh[nj][s2 + 1]);
                    MMA16816(acc[mi][ni], ah[mi], bl[nj][s2], bl[nj][s2 + 1]);
                    MMA16816(acc[mi][ni], al[mi], bh[nj][s2], bh[nj][s2 + 1]);
                }
        }
    }

    // ---- epilogue (mapping validated in R3) ----
    const int gid = lane >> 2, tig = lane & 3;
    #pragma unroll
    for (int mi = 0; mi < 4; mi++)
        #pragma unroll
        for (int ni = 0; ni < 4; ni++) {
            int r0 = m0 + wm * 64 + mi * 16 + gid;
            int c0 = n0 + wn * 32 + ni * 8 + tig * 2;
            float b0 = bias[c0], b1 = bias[c0 + 1];
            #pragma unroll
            for (int half = 0; half < 2; half++) {
                int r = r0 + half * 8;
                float v0 = acc[mi][ni][half * 2 + 0] + b0;
                float v1 = acc[mi][ni][half * 2 + 1] + b1;
                size_t idx = (size_t)r * ldout + c0;
                if (epi == 0) {
                    outF[idx] = v0; outF[idx + 1] = v1;
                } else if (epi == 1) {
                    outF[idx]     = v0 + res[idx];
                    outF[idx + 1] = v1 + res[idx + 1];
                } else {
                    v0 = fmaxf(v0, 0.f); v1 = fmaxf(v1, 0.f);
                    __nv_bfloat16 h0 = __float2bfloat16(v0);
                    __nv_bfloat16 h1 = __float2bfloat16(v1);
                    outHi[idx]     = h0;
                    outHi[idx + 1] = h1;
                    outLo[idx]     = __float2bfloat16(v0 - __bfloat162float(h0));
                    outLo[idx + 1] = __float2bfloat16(v1 - __bfloat162float(h1));
                }
            }
        }
}

// ---------------- LayerNorm (row = block). mode 0: bf16 split; mode 1: fp32 ----------------
__global__ __launch_bounds__(256)
void ln_kernel(const float* __restrict__ x, const float* __restrict__ g, const float* __restrict__ b,
               __nv_bfloat16* hi, __nv_bfloat16* lo, float* outf, int mode)
{
    __shared__ float red[16];
    const int row = blockIdx.x, tid = threadIdx.x;
    float4 v = ((const float4*)(x + (size_t)row * NFEAT))[tid];
    float s  = v.x + v.y + v.z + v.w;
    float sq = v.x * v.x + v.y * v.y + v.z * v.z + v.w * v.w;
    #pragma unroll
    for (int o = 16; o; o >>= 1) { s += __shfl_xor_sync(~0u, s, o); sq += __shfl_xor_sync(~0u, sq, o); }
    if ((tid & 31) == 0) { red[tid >> 5] = s; red[8 + (tid >> 5)] = sq; }
    __syncthreads();
    if (tid == 0) {
        float a = 0.f, c = 0.f;
        #pragma unroll
        for (int i = 0; i < 8; i++) { a += red[i]; c += red[8 + i]; }
        red[0] = a; red[8] = c;
    }
    __syncthreads();
    float mean = red[0] * (1.f / NFEAT);
    float var  = red[8] * (1.f / NFEAT) - mean * mean;
    float rs   = rsqrtf(var + 1e-5f);
    float4 gg = ((const float4*)g)[tid];
    float4 bb = ((const float4*)b)[tid];
    float y[4];
    y[0] = (v.x - mean) * rs * gg.x + bb.x;
    y[1] = (v.y - mean) * rs * gg.y + bb.y;
    y[2] = (v.z - mean) * rs * gg.z + bb.z;
    y[3] = (v.w - mean) * rs * gg.w + bb.w;
    size_t o0 = (size_t)row * NFEAT + tid * 4;
    if (mode == 0) {
        #pragma unroll
        for (int j = 0; j < 4; j++) {
            __nv_bfloat16 h = __float2bfloat16(y[j]);
            hi[o0 + j] = h;
            lo[o0 + j] = __float2bfloat16(y[j] - __bfloat162float(h));
        }
    } else {
        ((float4*)(outf + (size_t)row * NFEAT))[tid] = make_float4(y[0], y[1], y[2], y[3]);
    }
}

// ---------------- Attention: one block per (b,h), one query row per thread ----------------
__global__ __launch_bounds__(256, 1)
void attn_kernel(const float* __restrict__ qkv, const float* __restrict__ maskT,
                 __nv_bfloat16* __restrict__ oHi, __nv_bfloat16* __restrict__ oLo)
{
    extern __shared__ float sm[];
    float* sK = sm;
    float* sV = sm + TT * HDIM;
    const int b = blockIdx.x >> 4, h = blockIdx.x & 15;
    const int tid = threadIdx.x;
    const float scale = 0.125f;

    for (int i = tid; i < TT * HDIM; i += 256) {
        int s = i >> 6, d = i & 63;
        size_t base = (size_t)(s * BBATCH + b) * (3 * NFEAT) + h * HDIM + d;
        sK[i] = qkv[base + NFEAT];
        sV[i] = qkv[base + 2 * NFEAT];
    }
    __syncthreads();

    const int t = tid;
    float q[64], o[64];
    size_t qb = (size_t)(t * BBATCH + b) * (3 * NFEAT) + h * HDIM;
    #pragma unroll
    for (int d = 0; d < 64; d++) { q[d] = qkv[qb + d] * scale; o[d] = 0.f; }

    float m = -1e30f, ssum = 0.f;
    for (int s = 0; s < TT; s++) {
        const float4* k4 = (const float4*)(sK + s * HDIM);
        float x = 0.f;
        #pragma unroll
        for (int d4 = 0; d4 < 16; d4++) {
            float4 kk = k4[d4];
            x += q[d4 * 4 + 0] * kk.x + q[d4 * 4 + 1] * kk.y
               + q[d4 * 4 + 2] * kk.z + q[d4 * 4 + 3] * kk.w;
        }
        x += maskT[s * TT + t];
        float p;
        if (x > m) {
            float f = __expf(m - x);
            ssum *= f;
            #pragma unroll
            for (int d = 0; d < 64; d++) o[d] *= f;
            m = x; p = 1.f;
        } else {
            p = __expf(x - m);
        }
        ssum += p;
        const float4* v4 = (const float4*)(sV + s * HDIM);
        #pragma unroll
        for (int d4 = 0; d4 < 16; d4++) {
            float4 vv = v4[d4];
            o[d4 * 4 + 0] += p * vv.x; o[d4 * 4 + 1] += p * vv.y;
            o[d4 * 4 + 2] += p * vv.z; o[d4 * 4 + 3] += p * vv.w;
        }
    }
    float inv = 1.f / ssum;
    size_t ob = (size_t)(t * BBATCH + b) * NFEAT + h * HDIM;
    #pragma unroll
    for (int d = 0; d < 64; d++) {
        float v = o[d] * inv;
        __nv_bfloat16 hh = __float2bfloat16(v);
        oHi[ob + d] = hh;
        oLo[ob + d] = __float2bfloat16(v - __bfloat162float(hh));
    }
}

// ---------------- small utility kernels ----------------
__global__ void split_kernel(const float* __restrict__ src, __nv_bfloat16* __restrict__ hi,
                             __nv_bfloat16* __restrict__ lo, int n4)
{
    int i = blockIdx.x * 256 + threadIdx.x;
    if (i >= n4) return;
    float4 v = ((const float4*)src)[i];
    float a[4] = { v.x, v.y, v.z, v.w };
    size_t o = (size_t)i * 4;
    #pragma unroll
    for (int j = 0; j < 4; j++) {
        __nv_bfloat16 h = __float2bfloat16(a[j]);
        hi[o + j] = h;
        lo[o + j] = __float2bfloat16(a[j] - __bfloat162float(h));
    }
}

__global__ void copy_kernel(const float* __restrict__ src, float* __restrict__ dst, int n4)
{
    int i = blockIdx.x * 256 + threadIdx.x;
    if (i < n4) ((float4*)dst)[i] = ((const float4*)src)[i];
}

__global__ void maskT_kernel(const float* __restrict__ m, float* __restrict__ mt)
{
    int i = blockIdx.x * 256 + threadIdx.x;
    int t = i >> 8, s = i & 255;
    mt[s * TT + t] = m[i];
}

// ---------------- host driver ----------------
extern "C" void kernel_launch(void* const* d_in, const int* in_sizes, int n_in,
                              void* d_out, int out_size)
{
    const float* src   = (const float*)d_in[0];
    const float* mask  = (const float*)d_in[1];
    const float* Wqkv  = (const float*)d_in[2];
    const float* bqkv  = (const float*)d_in[3];
    const float* Wo    = (const float*)d_in[4];
    const float* bo    = (const float*)d_in[5];
    const float* ln1g  = (const float*)d_in[6];
    const float* ln1b  = (const float*)d_in[7];
    const float* ln2g  = (const float*)d_in[8];
    const float* ln2b  = (const float*)d_in[9];
    const float* W1    = (const float*)d_in[10];
    const float* b1    = (const float*)d_in[11];
    const float* W2    = (const float*)d_in[12];
    const float* b2    = (const float*)d_in[13];
    const float* lnfg  = (const float*)d_in[14];
    const float* lnfb  = (const float*)d_in[15];
    float* out = (float*)d_out;

    void *p_whi, *p_wlo, *p_hhi, *p_hlo, *p_fhi, *p_flo, *p_qkv, *p_x, *p_mt;
    cudaGetSymbolAddress(&p_whi, g_whi);
    cudaGetSymbolAddress(&p_wlo, g_wlo);
    cudaGetSymbolAddress(&p_hhi, g_hhi);
    cudaGetSymbolAddress(&p_hlo, g_hlo);
    cudaGetSymbolAddress(&p_fhi, g_fhi);
    cudaGetSymbolAddress(&p_flo, g_flo);
    cudaGetSymbolAddress(&p_qkv, g_qkv);
    cudaGetSymbolAddress(&p_x,   g_x);
    cudaGetSymbolAddress(&p_mt,  g_maskT);
    __nv_bfloat16* whi = (__nv_bfloat16*)p_whi;
    __nv_bfloat16* wlo = (__nv_bfloat16*)p_wlo;
    __nv_bfloat16* hhi = (__nv_bfloat16*)p_hhi;
    __nv_bfloat16* hlo = (__nv_bfloat16*)p_hlo;
    __nv_bfloat16* fhi = (__nv_bfloat16*)p_fhi;
    __nv_bfloat16* flo = (__nv_bfloat16*)p_flo;
    float* qkv = (float*)p_qkv;
    float* x   = (float*)p_x;
    float* mt  = (float*)p_mt;

    cudaFuncSetAttribute(attn_kernel, cudaFuncAttributeMaxDynamicSharedMemorySize,
                         2 * TT * HDIM * (int)sizeof(float));
    cudaFuncSetAttribute(gemm3p, cudaFuncAttributeMaxDynamicSharedMemorySize, SMEM_G);

    auto splitw = [&](const float* s, size_t off, size_t len) {
        int n4 = (int)(len / 4);
        split_kernel<<<(n4 + 255) / 256, 256>>>(s, whi + off, wlo + off, n4);
    };

    // Launch order arranged so the first gemm3p sits at a small launch index
    // (ncu capture window): [0]splitWqkv [1]copy [2]maskT [3]ln [4]splitWo [5]gemmQKV
    splitw(Wqkv, 0, LEN_WQKV);                                                     // 0
    copy_kernel<<<(MROWS * NFEAT / 4 + 255) / 256, 256>>>(src, x, MROWS * NFEAT / 4); // 1
    maskT_kernel<<<TT * TT / 256, 256>>>(mask, mt);                                // 2

    for (int l = 0; l < LLAY; l++) {
        // --- attention block ---
        ln_kernel<<<MROWS, 256>>>(x, ln1g + l * NFEAT, ln1b + l * NFEAT, hhi, hlo, nullptr, 0); // 3
        if (l == 0) splitw(Wo, OFF_WO, LEN_WO);                                    // 4
        gemm3p<<<dim3(3 * NFEAT / 128, MROWS / 128), 256, SMEM_G>>>(               // 5  <- profiled
            hhi, hlo,
            whi + (size_t)l * 3 * NFEAT * NFEAT, wlo + (size_t)l * 3 * NFEAT * NFEAT,
            NFEAT, 3 * NFEAT, bqkv + l * 3 * NFEAT,
            nullptr, qkv, nullptr, nullptr, 0);
        attn_kernel<<<BBATCH * NHEAD, 256, 2 * TT * HDIM * sizeof(float)>>>(qkv, mt, hhi, hlo);
        gemm3p<<<dim3(NFEAT / 128, MROWS / 128), 256, SMEM_G>>>(
            hhi, hlo,
            whi + OFF_WO + (size_t)l * NFEAT * NFEAT, wlo + OFF_WO + (size_t)l * NFEAT * NFEAT,
            NFEAT, NFEAT, bo + l * NFEAT,
            x, x, nullptr, nullptr, 1);
        // --- FFN block ---
        ln_kernel<<<MROWS, 256>>>(x, ln2g + l * NFEAT, ln2b + l * NFEAT, hhi, hlo, nullptr, 0);
        if (l == 0) { splitw(W1, OFF_W1, LEN_W1); splitw(W2, OFF_W2, LEN_W2); }
        gemm3p<<<dim3(FFD / 128, MROWS / 128), 256, SMEM_G>>>(
            hhi, hlo,
            whi + OFF_W1 + (size_t)l * FFD * NFEAT, wlo + OFF_W1 + (size_t)l * FFD * NFEAT,
            NFEAT, FFD, b1 + l * FFD,
            nullptr, nullptr, fhi, flo, 2);
        gemm3p<<<dim3(NFEAT / 128, MROWS / 128), 256, SMEM_G>>>(
            fhi, flo,
            whi + OFF_W2 + (size_t)l * NFEAT * FFD, wlo + OFF_W2 + (size_t)l * NFEAT * FFD,
            FFD, NFEAT, b2 + l * NFEAT,
            x, x, nullptr, nullptr, 1);
    }
    ln_kernel<<<MROWS, 256>>>(x, lnfg, lnfb, nullptr, nullptr, out, 1);
}